// round 15
// baseline (speedup 1.0000x reference)
#include <cuda_runtime.h>
#include <cstdint>

// FM second-order term via split-TF32 mma.sync (m16n8k8), single kernel.
//   sum_emb = features @ W  (M=16384, K=200->208, N=64)
//   x = hi+lo (tf32 split in regs); x@W ~ Ah@Bh + Ah@Bl + Al@Bh, fp32 accum.
//   out[b] = sum_e sum_emb[b,e]^2 - sum_f features[b,f]^2 * w2sum[f]
// R15: R10's lean mainloop (B as packed frag planes -> 2 LDS.128/kstep)
// with B conversion done IN-CTA from smem only: cp.async Braw into the tail
// of the Bfrag region, LDS-read all items to regs, barrier, split+STS.128
// (aliasing-safe). No prep kernel, no LDG gather. A double-buffered.
// 512 thr, 16 warps = mg4 x ng4, warp tile m32 x n16, full K (26 k8-steps).

typedef unsigned long long ull;

constexpr int F_DIM = 200;
constexpr int E_DIM = 64;
constexpr int MTILE = 128;
constexpr int THREADS = 512;
constexpr int NS = 26;               // k8-steps (208 >= 200)

constexpr int SA_F = 212;            // A row stride (floats; 848B)
constexpr int SM_A    = 0;           // 128*848 = 108544
constexpr int SM_B    = 108544;      // frag planes: 208 blk * 512 = 106496
constexpr int SM_BRAW = 155136;      // = SM_B + 46592; 208*288 = 59904 (tail)
constexpr int SM_W2S  = 215040;      // 200*4
constexpr int SM_SQS  = 215840;      // 128*4
constexpr int SM_PART = 216352;      // 512*4
constexpr int SMEM_TOTAL = 218400;

__device__ __forceinline__ uint32_t smem_u32(const void* p) {
    return (uint32_t)__cvta_generic_to_shared(p);
}
__device__ __forceinline__ void cp_async16(uint32_t s, const void* g) {
    asm volatile("cp.async.cg.shared.global [%0], [%1], 16;" :: "r"(s), "l"(g));
}
__device__ __forceinline__ float lds32f(uint32_t a) {
    float v; asm volatile("ld.shared.f32 %0, [%1];" : "=f"(v) : "r"(a)); return v;
}
__device__ __forceinline__ uint4 lds128(uint32_t a) {
    uint4 v;
    asm volatile("ld.shared.v4.b32 {%0,%1,%2,%3}, [%4];"
                 : "=r"(v.x), "=r"(v.y), "=r"(v.z), "=r"(v.w) : "r"(a));
    return v;
}
__device__ __forceinline__ void split13(float x, uint32_t& hi, uint32_t& lo) {
    hi = __float_as_uint(x) & 0xFFFFE000u;
    lo = __float_as_uint(x - __uint_as_float(hi));
}
__device__ __forceinline__ void mma_tf32(float* c, uint32_t a0, uint32_t a1,
                                         uint32_t a2, uint32_t a3,
                                         uint32_t b0, uint32_t b1) {
    asm volatile(
        "mma.sync.aligned.m16n8k8.row.col.f32.tf32.tf32.f32 "
        "{%0,%1,%2,%3}, {%4,%5,%6,%7}, {%8,%9}, {%0,%1,%2,%3};"
        : "+f"(c[0]), "+f"(c[1]), "+f"(c[2]), "+f"(c[3])
        : "r"(a0), "r"(a1), "r"(a2), "r"(a3), "r"(b0), "r"(b1));
}

__global__ void __launch_bounds__(THREADS, 1)
fm_kernel(const float* __restrict__ features,
          const float* __restrict__ W,
          float* __restrict__ out)
{
    extern __shared__ __align__(16) char smem[];
    const uint32_t sb = smem_u32(smem);
    const int tid = threadIdx.x;
    const int w = tid >> 5, lane = tid & 31;
    const int mg = w >> 2, ng = w & 3;          // warp: rows 32mg, cols 16ng
    const int gr = lane >> 2, gk = lane & 3;

    float* w2s  = (float*)(smem + SM_W2S);
    float* sqs  = (float*)(smem + SM_SQS);
    float* part = (float*)(smem + SM_PART);

    const size_t rowbase = (size_t)blockIdx.x * MTILE;
    const float* fblk = features + rowbase * F_DIM;

    // ---- cp.async: B raw FIRST (group 0), then A (group 1)
    // Braw: 200 rows x 16 chunks of 16B, row stride 288B, in Bfrag tail
    #pragma unroll
    for (int i = 0; i < 7; ++i) {
        const int p = tid + i * THREADS;
        if (p < 3200) {
            const int row = p >> 4, ch = p & 15;
            cp_async16(sb + SM_BRAW + row * 288 + ch * 16,
                       W + row * E_DIM + ch * 4);
        }
    }
    asm volatile("cp.async.commit_group;");
    // A: 128 rows x 50 chunks of 16B, row stride 848B
    #pragma unroll
    for (int i = 0; i < 13; ++i) {
        const int p = tid + i * THREADS;
        if (p < 6400) {
            const int row = p / 50, ch = p - row * 50;
            cp_async16(sb + SM_A + row * 848 + ch * 16,
                       fblk + row * F_DIM + ch * 4);
        }
    }
    asm volatile("cp.async.commit_group;");

    // ---- pads (regions not touched by cp.async)
    {   // A cols [200,208)
        const int row = tid >> 2, c0 = 200 + (tid & 3) * 2;
        *(float2*)(smem + SM_A + (row * SA_F + c0) * 4) = make_float2(0.f, 0.f);
    }
    if (tid < 144)   // Braw rows [200,208): 8*288 = 2304 B
        *(uint4*)(smem + SM_BRAW + 200 * 288 + tid * 16) = make_uint4(0, 0, 0, 0);

    // ---- wait Braw only; A still in flight during conversion
    asm volatile("cp.async.wait_group 1;" ::: "memory");
    __syncthreads();

    // ---- B conversion, LDS-only. Frag block bi = t*26+s; lane l needs
    // b0 = Braw[8s+(l&3)][8t+(l>>2)], b1 = row+4. Read ALL to regs first.
    float r0v[13], r1v[13];
    #pragma unroll
    for (int it = 0; it < 13; ++it) {
        const int bi = w + it * 16;              // 0..207
        const int t = bi / 26, s = bi - 26 * t;
        const uint32_t a = sb + SM_BRAW +
            (uint32_t)((8 * s + (lane & 3)) * 288 + (8 * t + (lane >> 2)) * 4);
        r0v[it] = lds32f(a);
        r1v[it] = lds32f(a + 4 * 288);
    }
    __syncthreads();   // all Braw reads done before frag writes (aliasing)
    #pragma unroll
    for (int it = 0; it < 13; ++it) {
        const int bi = w + it * 16;
        uint32_t b0h, b0l, b1h, b1l;
        split13(r0v[it], b0h, b0l);
        split13(r1v[it], b1h, b1l);
        *(uint4*)(smem + SM_B + bi * 512 + lane * 16) =
            make_uint4(b0h, b1h, b0l, b1l);
    }

    asm volatile("cp.async.wait_group 0;" ::: "memory");
    __syncthreads();

    // ---- MMA mainloop: warp m32 x n16, 26 k8-steps, double-buffered
    const uint32_t aB = sb + SM_A + (uint32_t)(((32 * mg + gr) * SA_F + gk) * 4);
    const uint32_t bB = sb + SM_B + (uint32_t)((2 * ng * 26) * 512 + lane * 16);

    float c[2][2][4];
    #pragma unroll
    for (int mi = 0; mi < 2; ++mi)
        #pragma unroll
        for (int j = 0; j < 2; ++j)
            #pragma unroll
            for (int q = 0; q < 4; ++q) c[mi][j][q] = 0.f;

    float a_c[8], a_n[8];
    uint4 B0c, B1c, B0n, B1n;
    #pragma unroll
    for (int u = 0; u < 4; ++u)
        #pragma unroll
        for (int v = 0; v < 2; ++v)
            a_c[u * 2 + v] = lds32f(aB + (uint32_t)(v * 16 + u * 8 * SA_F * 4));
    B0c = lds128(bB);
    B1c = lds128(bB + 13312);

    #pragma unroll
    for (int s = 0; s < NS; ++s) {
        const int sn = (s + 1 < NS) ? s + 1 : 0;
        #pragma unroll
        for (int u = 0; u < 4; ++u)
            #pragma unroll
            for (int v = 0; v < 2; ++v)
                a_n[u * 2 + v] =
                    lds32f(aB + (uint32_t)(sn * 32 + v * 16 + u * 8 * SA_F * 4));
        B0n = lds128(bB + sn * 512);
        B1n = lds128(bB + 13312 + sn * 512);

        uint32_t ah[8], al[8];
        #pragma unroll
        for (int q = 0; q < 8; ++q) split13(a_c[q], ah[q], al[q]);

        // hh (4 independent accums), then hl, then lh
        mma_tf32(c[0][0], ah[0], ah[2], ah[1], ah[3], B0c.x, B0c.y);
        mma_tf32(c[0][1], ah[0], ah[2], ah[1], ah[3], B1c.x, B1c.y);
        mma_tf32(c[1][0], ah[4], ah[6], ah[5], ah[7], B0c.x, B0c.y);
        mma_tf32(c[1][1], ah[4], ah[6], ah[5], ah[7], B1c.x, B1c.y);

        mma_tf32(c[0][0], ah[0], ah[2], ah[1], ah[3], B0c.z, B0c.w);
        mma_tf32(c[0][1], ah[0], ah[2], ah[1], ah[3], B1c.z, B1c.w);
        mma_tf32(c[1][0], ah[4], ah[6], ah[5], ah[7], B0c.z, B0c.w);
        mma_tf32(c[1][1], ah[4], ah[6], ah[5], ah[7], B1c.z, B1c.w);

        mma_tf32(c[0][0], al[0], al[2], al[1], al[3], B0c.x, B0c.y);
        mma_tf32(c[0][1], al[0], al[2], al[1], al[3], B1c.x, B1c.y);
        mma_tf32(c[1][0], al[4], al[6], al[5], al[7], B0c.x, B0c.y);
        mma_tf32(c[1][1], al[4], al[6], al[5], al[7], B1c.x, B1c.y);

        #pragma unroll
        for (int q = 0; q < 8; ++q) a_c[q] = a_n[q];
        B0c = B0n; B1c = B1n;
    }

    // ---- epilogue: per-row sum of squares over this warp's 16 cols
    {
        float su[4];
        #pragma unroll
        for (int u = 0; u < 4; ++u) {
            const int mi = u >> 1, cr = (u & 1) * 2;
            su[u] = c[mi][0][cr] * c[mi][0][cr] + c[mi][0][cr + 1] * c[mi][0][cr + 1]
                  + c[mi][1][cr] * c[mi][1][cr] + c[mi][1][cr + 1] * c[mi][1][cr + 1];
        }
        #pragma unroll
        for (int u = 0; u < 4; ++u) {
            su[u] += __shfl_xor_sync(0xffffffffu, su[u], 1);
            su[u] += __shfl_xor_sync(0xffffffffu, su[u], 2);
        }
        if (gk == 0) {
            #pragma unroll
            for (int u = 0; u < 4; ++u)
                part[ng * 128 + 32 * mg + 8 * u + gr] = su[u];
        }
    }

    // ---- w2sum from global W (L2-hot by now), post-mainloop
    if (tid < F_DIM) {
        const float4* wr = (const float4*)(W + (size_t)tid * E_DIM);
        float s = 0.f;
        #pragma unroll
        for (int i = 0; i < E_DIM / 4; ++i) {
            float4 v = wr[i];
            s = fmaf(v.x, v.x, s); s = fmaf(v.y, v.y, s);
            s = fmaf(v.z, v.z, s); s = fmaf(v.w, v.w, s);
        }
        w2s[tid] = s;
    }
    __syncthreads();

    // ---- sq term from smem A (raw fp32, exact)
    {
        const int row = tid >> 2, q = tid & 3;
        const uint32_t aRow = sb + SM_A + (uint32_t)(row * 848);
        float s0 = 0.f, s1 = 0.f;
        #pragma unroll
        for (int j = 0; j < 50; j += 2) {
            const int f0 = q + 4 * j, f1 = q + 4 * (j + 1);
            const float x0 = lds32f(aRow + f0 * 4);
            const float x1 = lds32f(aRow + f1 * 4);
            s0 = fmaf(x0 * x0, w2s[f0], s0);
            s1 = fmaf(x1 * x1, w2s[f1], s1);
        }
        float sq = s0 + s1;
        sq += __shfl_xor_sync(0xffffffffu, sq, 1);
        sq += __shfl_xor_sync(0xffffffffu, sq, 2);
        if (q == 0) sqs[row] = sq;
    }
    __syncthreads();

    if (tid < MTILE)
        out[rowbase + tid] = part[tid] + part[128 + tid] + part[256 + tid] +
                             part[384 + tid] - sqs[tid];
}

extern "C" void kernel_launch(void* const* d_in, const int* in_sizes, int n_in,
                              void* d_out, int out_size)
{
    const float* features = (const float*)d_in[0];
    const float* W        = (const float*)d_in[1];
    if (n_in >= 2 && in_sizes[0] < in_sizes[1]) {
        features = (const float*)d_in[1];
        W        = (const float*)d_in[0];
    }
    float* out = (float*)d_out;

    cudaFuncSetAttribute(fm_kernel,
                         cudaFuncAttributeMaxDynamicSharedMemorySize, SMEM_TOTAL);

    const int B = out_size;              // 16384
    const int blocks = B / MTILE;        // 128 -> 1 CTA/SM, single wave
    fm_kernel<<<blocks, THREADS, SMEM_TOTAL>>>(features, W, out);
}

// round 16
// speedup vs baseline: 1.1577x; 1.1577x over previous
#include <cuda_runtime.h>
#include <cstdint>

// FM second-order term via split-TF32 mma.sync (m16n8k8), single kernel.
//   sum_emb = features @ W  (M=16384, K=200, N=64)
//   per operand: hi = mask13(x), lo = x-hi (registers, HW truncates to tf32)
//   x@W ~ Ah@Bh + Ah@Bl + Al@Bh, fp32 accum.
//   out[b] = sum_e sum_emb[b,e]^2 - sum_f features[b,f]^2 * w2sum[f]
// R16 = R14 + k-banded staging pipeline: A cp.async split into 3 column
// bands (cols 0-63 / 64-135 / 136-199) with separate commit groups; the
// MMA mainloop runs in 3 segments gated by wait_group -> MMAs on band 0
// overlap the DRAM flight of bands 1-2. K=200 = 25 k8-steps exactly (no
// padding at all). 512 thr, 16 warps = mg4 x ng4, warp tile m32 x n16.

typedef unsigned long long ull;

constexpr int F_DIM = 200;
constexpr int E_DIM = 64;
constexpr int MTILE = 128;
constexpr int THREADS = 512;

constexpr int SA_F = 212;            // A row stride (floats; 848B)
constexpr int SM_A    = 0;           // 128*848 = 108544
constexpr int SM_B    = 108544;      // Braw: 200*288 = 57600 (stride 72 fl)
constexpr int SM_W2S  = 166144;      // 200*4
constexpr int SM_SQS  = 166944;      // 128*4
constexpr int SM_PART = 167456;      // 512*4
constexpr int SMEM_TOTAL = 169504;

__device__ __forceinline__ uint32_t smem_u32(const void* p) {
    return (uint32_t)__cvta_generic_to_shared(p);
}
__device__ __forceinline__ void cp_async16(uint32_t s, const void* g) {
    asm volatile("cp.async.cg.shared.global [%0], [%1], 16;" :: "r"(s), "l"(g));
}
__device__ __forceinline__ float lds32f(uint32_t a) {
    float v; asm volatile("ld.shared.f32 %0, [%1];" : "=f"(v) : "r"(a)); return v;
}
__device__ __forceinline__ void split13(float x, uint32_t& hi, uint32_t& lo) {
    hi = __float_as_uint(x) & 0xFFFFE000u;
    lo = __float_as_uint(x - __uint_as_float(hi));
}
__device__ __forceinline__ void mma_tf32(float* c, uint32_t a0, uint32_t a1,
                                         uint32_t a2, uint32_t a3,
                                         uint32_t b0, uint32_t b1) {
    asm volatile(
        "mma.sync.aligned.m16n8k8.row.col.f32.tf32.tf32.f32 "
        "{%0,%1,%2,%3}, {%4,%5,%6,%7}, {%8,%9}, {%0,%1,%2,%3};"
        : "+f"(c[0]), "+f"(c[1]), "+f"(c[2]), "+f"(c[3])
        : "r"(a0), "r"(a1), "r"(a2), "r"(a3), "r"(b0), "r"(b1));
}

// copy one A column band [c0, c0+CNT) chunks (16B each) for all 128 rows
template <int C0, int CNT>
__device__ __forceinline__ void stage_A_band(uint32_t sb, const float* fblk,
                                             int tid) {
    constexpr int TOT = 128 * CNT;
    #pragma unroll
    for (int i = 0; i < (TOT + THREADS - 1) / THREADS; ++i) {
        const int p = tid + i * THREADS;
        if (TOT % THREADS == 0 || p < TOT) {
            const int row = p / CNT, ch = C0 + (p - row * CNT);
            cp_async16(sb + SM_A + row * 848 + ch * 16,
                       fblk + row * F_DIM + ch * 4);
        }
    }
    asm volatile("cp.async.commit_group;");
}

// one mainloop segment: k8-steps [S0, S1), double-buffered fragments
template <int S0, int S1>
__device__ __forceinline__ void run_seg(uint32_t aB, uint32_t bB,
                                        float c[2][2][4]) {
    float a_c[8], b_c[4], a_n[8], b_n[4];
    #pragma unroll
    for (int u = 0; u < 4; ++u)
        #pragma unroll
        for (int v = 0; v < 2; ++v)
            a_c[u * 2 + v] =
                lds32f(aB + (uint32_t)(S0 * 32 + v * 16 + u * 8 * SA_F * 4));
    #pragma unroll
    for (int j = 0; j < 2; ++j)
        #pragma unroll
        for (int h = 0; h < 2; ++h)
            b_c[j * 2 + h] =
                lds32f(bB + (uint32_t)((S0 * 8 + h * 4) * 288 + j * 32));

    #pragma unroll
    for (int s = S0; s < S1; ++s) {
        const int sn = (s + 1 < S1) ? s + 1 : S0;   // dummy-wrap in-segment
        #pragma unroll
        for (int u = 0; u < 4; ++u)
            #pragma unroll
            for (int v = 0; v < 2; ++v)
                a_n[u * 2 + v] =
                    lds32f(aB + (uint32_t)(sn * 32 + v * 16 + u * 8 * SA_F * 4));
        #pragma unroll
        for (int j = 0; j < 2; ++j)
            #pragma unroll
            for (int h = 0; h < 2; ++h)
                b_n[j * 2 + h] =
                    lds32f(bB + (uint32_t)((sn * 8 + h * 4) * 288 + j * 32));

        uint32_t ah[8], al[8], bh[4], bl[4];
        #pragma unroll
        for (int q = 0; q < 8; ++q) split13(a_c[q], ah[q], al[q]);
        #pragma unroll
        for (int q = 0; q < 4; ++q) split13(b_c[q], bh[q], bl[q]);

        // 12 MMAs: hh (4 independent accums), hl, lh
        mma_tf32(c[0][0], ah[0], ah[2], ah[1], ah[3], bh[0], bh[1]);
        mma_tf32(c[0][1], ah[0], ah[2], ah[1], ah[3], bh[2], bh[3]);
        mma_tf32(c[1][0], ah[4], ah[6], ah[5], ah[7], bh[0], bh[1]);
        mma_tf32(c[1][1], ah[4], ah[6], ah[5], ah[7], bh[2], bh[3]);

        mma_tf32(c[0][0], ah[0], ah[2], ah[1], ah[3], bl[0], bl[1]);
        mma_tf32(c[0][1], ah[0], ah[2], ah[1], ah[3], bl[2], bl[3]);
        mma_tf32(c[1][0], ah[4], ah[6], ah[5], ah[7], bl[0], bl[1]);
        mma_tf32(c[1][1], ah[4], ah[6], ah[5], ah[7], bl[2], bl[3]);

        mma_tf32(c[0][0], al[0], al[2], al[1], al[3], bh[0], bh[1]);
        mma_tf32(c[0][1], al[0], al[2], al[1], al[3], bh[2], bh[3]);
        mma_tf32(c[1][0], al[4], al[6], al[5], al[7], bh[0], bh[1]);
        mma_tf32(c[1][1], al[4], al[6], al[5], al[7], bh[2], bh[3]);

        #pragma unroll
        for (int q = 0; q < 8; ++q) a_c[q] = a_n[q];
        #pragma unroll
        for (int q = 0; q < 4; ++q) b_c[q] = b_n[q];
    }
}

__global__ void __launch_bounds__(THREADS, 1)
fm_kernel(const float* __restrict__ features,
          const float* __restrict__ W,
          float* __restrict__ out)
{
    extern __shared__ __align__(16) char smem[];
    const uint32_t sb = smem_u32(smem);
    const int tid = threadIdx.x;
    const int w = tid >> 5, lane = tid & 31;
    const int mg = w >> 2, ng = w & 3;          // warp: rows 32mg, cols 16ng
    const int gr = lane >> 2, gk = lane & 3;

    float* w2s  = (float*)(smem + SM_W2S);
    float* sqs  = (float*)(smem + SM_SQS);
    float* part = (float*)(smem + SM_PART);

    const size_t rowbase = (size_t)blockIdx.x * MTILE;
    const float* fblk = features + rowbase * F_DIM;

    // ---- staging: B (g0, L2-hot), then A bands (g1,g2,g3)
    // B raw fp32: 200 rows x 16 chunks, row stride 288B
    #pragma unroll
    for (int i = 0; i < 7; ++i) {
        const int p = tid + i * THREADS;
        if (p < 3200) {
            const int row = p >> 4, ch = p & 15;
            cp_async16(sb + SM_B + row * 288 + ch * 16,
                       W + row * E_DIM + ch * 4);
        }
    }
    asm volatile("cp.async.commit_group;");
    stage_A_band<0, 16>(sb, fblk, tid);    // cols   0..63  -> steps 0..7
    stage_A_band<16, 18>(sb, fblk, tid);   // cols  64..135 -> steps 8..16
    stage_A_band<34, 16>(sb, fblk, tid);   // cols 136..199 -> steps 17..24

    // ---- mainloop bases
    const uint32_t aB = sb + SM_A + (uint32_t)(((32 * mg + gr) * SA_F + gk) * 4);
    const uint32_t bB = sb + SM_B + (uint32_t)((gk * 72 + 16 * ng + gr) * 4);

    float c[2][2][4];
    #pragma unroll
    for (int mi = 0; mi < 2; ++mi)
        #pragma unroll
        for (int j = 0; j < 2; ++j)
            #pragma unroll
            for (int q = 0; q < 4; ++q) c[mi][j][q] = 0.f;

    // ---- segment 0: B + band0 landed (2 groups still pending)
    asm volatile("cp.async.wait_group 2;" ::: "memory");
    __syncthreads();
    run_seg<0, 8>(aB, bB, c);

    // ---- segment 1: band1 landed
    asm volatile("cp.async.wait_group 1;" ::: "memory");
    __syncthreads();
    run_seg<8, 17>(aB, bB, c);

    // ---- segment 2: band2 landed
    asm volatile("cp.async.wait_group 0;" ::: "memory");
    __syncthreads();
    run_seg<17, 25>(aB, bB, c);

    // ---- epilogue: per-row sum of squares over this warp's 16 cols
    {
        float su[4];
        #pragma unroll
        for (int u = 0; u < 4; ++u) {
            const int mi = u >> 1, cr = (u & 1) * 2;
            su[u] = c[mi][0][cr] * c[mi][0][cr] + c[mi][0][cr + 1] * c[mi][0][cr + 1]
                  + c[mi][1][cr] * c[mi][1][cr] + c[mi][1][cr + 1] * c[mi][1][cr + 1];
        }
        #pragma unroll
        for (int u = 0; u < 4; ++u) {
            su[u] += __shfl_xor_sync(0xffffffffu, su[u], 1);
            su[u] += __shfl_xor_sync(0xffffffffu, su[u], 2);
        }
        if (gk == 0) {
            #pragma unroll
            for (int u = 0; u < 4; ++u)
                part[ng * 128 + 32 * mg + 8 * u + gr] = su[u];
        }
    }

    // ---- w2sum from Braw smem (LDS only)
    if (tid < F_DIM) {
        float s = 0.f;
        #pragma unroll
        for (int i = 0; i < 16; ++i) {
            const float4 v = *(const float4*)(smem + SM_B + tid * 288 + i * 16);
            s = fmaf(v.x, v.x, s); s = fmaf(v.y, v.y, s);
            s = fmaf(v.z, v.z, s); s = fmaf(v.w, v.w, s);
        }
        w2s[tid] = s;
    }
    __syncthreads();

    // ---- sq term from smem A (raw fp32, exact)
    {
        const int row = tid >> 2, q = tid & 3;
        const uint32_t aRow = sb + SM_A + (uint32_t)(row * 848);
        float s0 = 0.f, s1 = 0.f;
        #pragma unroll
        for (int j = 0; j < 50; j += 2) {
            const int f0 = q + 4 * j, f1 = q + 4 * (j + 1);
            const float x0 = lds32f(aRow + f0 * 4);
            const float x1 = lds32f(aRow + f1 * 4);
            s0 = fmaf(x0 * x0, w2s[f0], s0);
            s1 = fmaf(x1 * x1, w2s[f1], s1);
        }
        float sq = s0 + s1;
        sq += __shfl_xor_sync(0xffffffffu, sq, 1);
        sq += __shfl_xor_sync(0xffffffffu, sq, 2);
        if (q == 0) sqs[row] = sq;
    }
    __syncthreads();

    if (tid < MTILE)
        out[rowbase + tid] = part[tid] + part[128 + tid] + part[256 + tid] +
                             part[384 + tid] - sqs[tid];
}

extern "C" void kernel_launch(void* const* d_in, const int* in_sizes, int n_in,
                              void* d_out, int out_size)
{
    const float* features = (const float*)d_in[0];
    const float* W        = (const float*)d_in[1];
    if (n_in >= 2 && in_sizes[0] < in_sizes[1]) {
        features = (const float*)d_in[1];
        W        = (const float*)d_in[0];
    }
    float* out = (float*)d_out;

    cudaFuncSetAttribute(fm_kernel,
                         cudaFuncAttributeMaxDynamicSharedMemorySize, SMEM_TOTAL);

    const int B = out_size;              // 16384
    const int blocks = B / MTILE;        // 128 -> 1 CTA/SM, single wave
    fm_kernel<<<blocks, THREADS, SMEM_TOTAL>>>(features, W, out);
}